// round 1
// baseline (speedup 1.0000x reference)
#include <cuda_runtime.h>

// Problem constants (fixed-shape problem)
#define NNODES 100000
#define NEDGES 3200000
#define F      64
#define BN_EPS 1e-5f

// ---------------- device scratch (no runtime allocation allowed) ----------------
__device__ int   g_counts[NNODES];
__device__ int   g_rowptr[NNODES + 1];
__device__ int   g_cursor[NNODES];
__device__ int   g_sorted[NEDGES];
__device__ __align__(16) float g_h[(size_t)NNODES * F];   // aggregated features
__device__ float g_W1f[F * F];                            // W1 with BN folded
__device__ float g_b1f[F];                                // b1 with BN folded

// ---------------- init: fold BN into layer-1 affine, zero histogram ----------------
__global__ void k_init(const float* __restrict__ W1, const float* __restrict__ b1,
                       const float* __restrict__ gamma, const float* __restrict__ beta,
                       const float* __restrict__ mean, const float* __restrict__ var) {
    int idx = blockIdx.x * blockDim.x + threadIdx.x;
    if (idx < NNODES) g_counts[idx] = 0;
    if (idx < F * F) {
        int j = idx & (F - 1);
        float s = gamma[j] * rsqrtf(var[j] + BN_EPS);
        g_W1f[idx] = W1[idx] * s;
        if (idx < F) g_b1f[idx] = (b1[idx] - mean[idx]) * s + beta[idx];
    }
}

// ---------------- histogram of destination degrees ----------------
__global__ void k_hist(const int* __restrict__ dst) {
    int e = blockIdx.x * blockDim.x + threadIdx.x;
    if (e < NEDGES) atomicAdd(&g_counts[dst[e]], 1);
}

// ---------------- single-block exclusive scan -> rowptr + cursor ----------------
__global__ void k_scan() {
    __shared__ int s[1024];
    const int t = threadIdx.x;
    const int C = (NNODES + 1023) / 1024;   // 98
    int beg = t * C;
    int end = min(beg + C, NNODES);
    int sum = 0;
    for (int i = beg; i < end; i++) sum += g_counts[i];
    s[t] = sum;
    __syncthreads();
    for (int off = 1; off < 1024; off <<= 1) {
        int v = (t >= off) ? s[t - off] : 0;
        __syncthreads();
        s[t] += v;
        __syncthreads();
    }
    int run = s[t] - sum;                   // exclusive prefix
    for (int i = beg; i < end; i++) {
        g_rowptr[i] = run;
        g_cursor[i] = run;
        run += g_counts[i];
    }
    if (t == 1023) g_rowptr[NNODES] = s[1023];
}

// ---------------- scatter src ids into CSR order ----------------
__global__ void k_scatter(const int* __restrict__ src, const int* __restrict__ dst) {
    int e = blockIdx.x * blockDim.x + threadIdx.x;
    if (e < NEDGES) {
        int d = dst[e];
        int pos = atomicAdd(&g_cursor[d], 1);
        g_sorted[pos] = src[e];
    }
}

// ---------------- gather: warp per node, float2 per lane ----------------
__global__ void k_gather(const float* __restrict__ x) {
    int warp = (blockIdx.x * blockDim.x + threadIdx.x) >> 5;
    int lane = threadIdx.x & 31;
    if (warp >= NNODES) return;
    const float2* __restrict__ xr = (const float2*)x;
    float2 acc = xr[warp * 32 + lane];      // self term: (1+eps)*x[i], eps=0
    int beg = g_rowptr[warp];
    int end = g_rowptr[warp + 1];
    int e = beg;
    for (; e + 4 <= end; e += 4) {
        int s0 = g_sorted[e + 0];
        int s1 = g_sorted[e + 1];
        int s2 = g_sorted[e + 2];
        int s3 = g_sorted[e + 3];
        float2 a0 = xr[s0 * 32 + lane];
        float2 a1 = xr[s1 * 32 + lane];
        float2 a2 = xr[s2 * 32 + lane];
        float2 a3 = xr[s3 * 32 + lane];
        acc.x += (a0.x + a1.x) + (a2.x + a3.x);
        acc.y += (a0.y + a1.y) + (a2.y + a3.y);
    }
    for (; e < end; e++) {
        float2 a = xr[g_sorted[e] * 32 + lane];
        acc.x += a.x;
        acc.y += a.y;
    }
    ((float2*)g_h)[warp * 32 + lane] = acc;
}

// ---------------- fused MLP: 128-node tiles, 16x16 threads, 8x4 microtiles ----------------
#define TM 128
#define XPITCH 65   // padded pitch to avoid smem bank conflicts on column reads

__device__ __forceinline__ void gemm64(const float* __restrict__ Xs, const float* __restrict__ Ws,
                                       float* __restrict__ Ys, const float* __restrict__ bias,
                                       int tx, int ty) {
    float acc[8][4];
    #pragma unroll
    for (int j = 0; j < 4; j++) {
        float b = bias[tx * 4 + j];
        #pragma unroll
        for (int i = 0; i < 8; i++) acc[i][j] = b;
    }
    #pragma unroll 8
    for (int k = 0; k < 64; k++) {
        float a[8], b[4];
        #pragma unroll
        for (int i = 0; i < 8; i++) a[i] = Xs[(ty * 8 + i) * XPITCH + k];
        #pragma unroll
        for (int j = 0; j < 4; j++) b[j] = Ws[k * 64 + tx * 4 + j];
        #pragma unroll
        for (int i = 0; i < 8; i++)
            #pragma unroll
            for (int j = 0; j < 4; j++) acc[i][j] += a[i] * b[j];
    }
    #pragma unroll
    for (int i = 0; i < 8; i++)
        #pragma unroll
        for (int j = 0; j < 4; j++)
            Ys[(ty * 8 + i) * XPITCH + tx * 4 + j] = fmaxf(acc[i][j], 0.f);
}

__device__ __forceinline__ void gemm64_head(const float* __restrict__ Xs, const float* __restrict__ Ws,
                                            const float* __restrict__ bias, const float* __restrict__ wl2,
                                            float* __restrict__ outs, int tx, int ty) {
    float acc[8][4];
    #pragma unroll
    for (int j = 0; j < 4; j++) {
        float b = bias[tx * 4 + j];
        #pragma unroll
        for (int i = 0; i < 8; i++) acc[i][j] = b;
    }
    #pragma unroll 8
    for (int k = 0; k < 64; k++) {
        float a[8], b[4];
        #pragma unroll
        for (int i = 0; i < 8; i++) a[i] = Xs[(ty * 8 + i) * XPITCH + k];
        #pragma unroll
        for (int j = 0; j < 4; j++) b[j] = Ws[k * 64 + tx * 4 + j];
        #pragma unroll
        for (int i = 0; i < 8; i++)
            #pragma unroll
            for (int j = 0; j < 4; j++) acc[i][j] += a[i] * b[j];
    }
    float w2r[4];
    #pragma unroll
    for (int j = 0; j < 4; j++) w2r[j] = wl2[tx * 4 + j];
    #pragma unroll
    for (int i = 0; i < 8; i++) {
        float s = 0.f;
        #pragma unroll
        for (int j = 0; j < 4; j++) s += fmaxf(acc[i][j], 0.f) * w2r[j];
        atomicAdd(&outs[ty * 8 + i], s);
    }
}

__global__ void k_mlp(const float* __restrict__ W2, const float* __restrict__ b2,
                      const float* __restrict__ Wl1, const float* __restrict__ bl1,
                      const float* __restrict__ Wl2, const float* __restrict__ bl2,
                      float* __restrict__ out) {
    extern __shared__ float sm[];
    float* X    = sm;                       // TM * XPITCH
    float* Y    = X + TM * XPITCH;          // TM * XPITCH
    float* W    = Y + TM * XPITCH;          // 64 * 64
    float* outs = W + 64 * 64;              // TM

    const int tid = threadIdx.x;
    const int tx = tid & 15;
    const int ty = tid >> 4;
    const int base = blockIdx.x * TM;

    // load h tile (float4, zero-padded past N)
    for (int i = tid; i < TM * 16; i += 256) {
        int row = i >> 4, c4 = i & 15;
        int node = base + row;
        float4 v = make_float4(0.f, 0.f, 0.f, 0.f);
        if (node < NNODES) v = ((const float4*)g_h)[node * 16 + c4];
        float* xp = &X[row * XPITCH + c4 * 4];
        xp[0] = v.x; xp[1] = v.y; xp[2] = v.z; xp[3] = v.w;
    }
    for (int i = tid; i < 4096; i += 256) W[i] = g_W1f[i];
    if (tid < TM) outs[tid] = bl2[0];
    __syncthreads();

    // layer 1: Y = relu(BN(X@W1 + b1))  (BN folded)
    gemm64(X, W, Y, g_b1f, tx, ty);
    __syncthreads();

    // layer 2: X = relu(Y@W2 + b2)
    for (int i = tid; i < 4096; i += 256) W[i] = W2[i];
    __syncthreads();
    gemm64(Y, W, X, b2, tx, ty);
    __syncthreads();

    // layers 3+4 fused: out += relu(X@Wl1 + bl1) @ Wl2, in three 64-col chunks
    for (int c = 0; c < 3; c++) {
        for (int i = tid; i < 4096; i += 256) {
            int k = i >> 6, j = i & 63;
            W[i] = Wl1[k * 192 + c * 64 + j];
        }
        __syncthreads();
        gemm64_head(X, W, bl1 + c * 64, Wl2 + c * 64, outs, tx, ty);
        __syncthreads();
    }

    if (tid < TM) {
        int node = base + tid;
        if (node < NNODES) out[node] = outs[tid];
    }
}

// ---------------- launch ----------------
extern "C" void kernel_launch(void* const* d_in, const int* in_sizes, int n_in,
                              void* d_out, int out_size) {
    const float* x     = (const float*)d_in[0];
    const int*   ei    = (const int*)  d_in[1];
    const float* W1    = (const float*)d_in[2];
    const float* b1    = (const float*)d_in[3];
    const float* gamma = (const float*)d_in[4];
    const float* beta  = (const float*)d_in[5];
    const float* mean  = (const float*)d_in[6];
    const float* var   = (const float*)d_in[7];
    const float* W2    = (const float*)d_in[8];
    const float* b2    = (const float*)d_in[9];
    const float* Wl1   = (const float*)d_in[10];
    const float* bl1   = (const float*)d_in[11];
    const float* Wl2   = (const float*)d_in[12];
    const float* bl2   = (const float*)d_in[13];
    float* out = (float*)d_out;

    const int* src = ei;             // edge_index[0]
    const int* dst = ei + NEDGES;    // edge_index[1]

    k_init<<<(NNODES + 255) / 256, 256>>>(W1, b1, gamma, beta, mean, var);
    k_hist<<<(NEDGES + 255) / 256, 256>>>(dst);
    k_scan<<<1, 1024>>>();
    k_scatter<<<(NEDGES + 255) / 256, 256>>>(src, dst);
    k_gather<<<(NNODES + 7) / 8, 256>>>(x);

    const int smem_mlp = (TM * XPITCH * 2 + 64 * 64 + TM) * (int)sizeof(float);
    cudaFuncSetAttribute(k_mlp, cudaFuncAttributeMaxDynamicSharedMemorySize, smem_mlp);
    k_mlp<<<(NNODES + TM - 1) / TM, 256, smem_mlp>>>(W2, b2, Wl1, bl1, Wl2, bl2, out);
}

// round 3
// speedup vs baseline: 1.0085x; 1.0085x over previous
#include <cuda_runtime.h>

// Problem constants (fixed-shape problem)
#define NNODES 100000
#define NEDGES 3200000
#define F      64
#define BN_EPS 1e-5f

typedef unsigned long long u64;

// ---------------- device scratch (no runtime allocation allowed) ----------------
__device__ int   g_counts[NNODES];
__device__ int   g_rowptr[NNODES + 1];
__device__ int   g_cursor[NNODES];
__device__ int   g_sorted[NEDGES];
__device__ __align__(16) float g_h[(size_t)NNODES * F];   // aggregated features
__device__ float g_W1f[F * F];                            // W1 with BN folded
__device__ float g_b1f[F];                                // b1 with BN folded

// ---------------- f32x2 packed-FMA helpers (Blackwell fp32x2 pipe) ----------------
__device__ __forceinline__ u64 pack2(float a, float b) {
    u64 r; asm("mov.b64 %0, {%1, %2};" : "=l"(r) : "f"(a), "f"(b)); return r;
}
__device__ __forceinline__ float2 unpack2(u64 v) {
    float2 f; asm("mov.b64 {%0, %1}, %2;" : "=f"(f.x), "=f"(f.y) : "l"(v)); return f;
}
__device__ __forceinline__ u64 fma2(u64 a, u64 b, u64 c) {
    u64 d; asm("fma.rn.f32x2 %0, %1, %2, %3;" : "=l"(d) : "l"(a), "l"(b), "l"(c)); return d;
}

// ---------------- init: fold BN into layer-1 affine, zero histogram ----------------
__global__ void k_init(const float* __restrict__ W1, const float* __restrict__ b1,
                       const float* __restrict__ gamma, const float* __restrict__ beta,
                       const float* __restrict__ mean, const float* __restrict__ var) {
    int idx = blockIdx.x * blockDim.x + threadIdx.x;
    if (idx < NNODES) g_counts[idx] = 0;
    if (idx < F * F) {
        int j = idx & (F - 1);
        float s = gamma[j] * rsqrtf(var[j] + BN_EPS);
        g_W1f[idx] = W1[idx] * s;
        if (idx < F) g_b1f[idx] = (b1[idx] - mean[idx]) * s + beta[idx];
    }
}

// ---------------- histogram of destination degrees (4 edges/thread) ----------------
__global__ void k_hist(const int4* __restrict__ dst4) {
    int t = blockIdx.x * blockDim.x + threadIdx.x;
    if (t < NEDGES / 4) {
        int4 d = dst4[t];
        atomicAdd(&g_counts[d.x], 1);
        atomicAdd(&g_counts[d.y], 1);
        atomicAdd(&g_counts[d.z], 1);
        atomicAdd(&g_counts[d.w], 1);
    }
}

// ---------------- single-block exclusive scan -> rowptr + cursor ----------------
__global__ void k_scan() {
    __shared__ int s[1024];
    const int t = threadIdx.x;
    const int C = 100;                      // 1000 threads * 100 = 100000
    int beg = t * C;
    int sum = 0;
    if (t < 1000) {
        const int4* c4 = (const int4*)&g_counts[beg];
        #pragma unroll 5
        for (int i = 0; i < C / 4; i++) {
            int4 v = c4[i];
            sum += v.x + v.y + v.z + v.w;
        }
    }
    s[t] = sum;
    __syncthreads();
    for (int off = 1; off < 1024; off <<= 1) {
        int v = (t >= off) ? s[t - off] : 0;
        __syncthreads();
        s[t] += v;
        __syncthreads();
    }
    int run = s[t] - sum;                   // exclusive prefix
    if (t < 1000) {
        for (int i = beg; i < beg + C; i++) {
            g_rowptr[i] = run;
            g_cursor[i] = run;
            run += g_counts[i];
        }
    }
    if (t == 1023) g_rowptr[NNODES] = s[1023];
}

// ---------------- scatter src ids into CSR order (4 edges/thread) ----------------
__global__ void k_scatter(const int4* __restrict__ src4, const int4* __restrict__ dst4) {
    int t = blockIdx.x * blockDim.x + threadIdx.x;
    if (t < NEDGES / 4) {
        int4 s = src4[t];
        int4 d = dst4[t];
        g_sorted[atomicAdd(&g_cursor[d.x], 1)] = s.x;
        g_sorted[atomicAdd(&g_cursor[d.y], 1)] = s.y;
        g_sorted[atomicAdd(&g_cursor[d.z], 1)] = s.z;
        g_sorted[atomicAdd(&g_cursor[d.w], 1)] = s.w;
    }
}

// ---------------- gather: half-warp per node, float4 per lane, 8-deep unroll ----------------
__global__ void __launch_bounds__(256) k_gather(const float4* __restrict__ x4) {
    int hw = (blockIdx.x * blockDim.x + threadIdx.x) >> 4;   // half-warp id = node
    int lane = threadIdx.x & 15;
    if (hw >= NNODES) return;
    float4 acc = __ldg(&x4[hw * 16 + lane]);                 // self term, eps=0
    int beg = g_rowptr[hw];
    int end = g_rowptr[hw + 1];
    int e = beg;
    for (; e + 8 <= end; e += 8) {
        int s[8];
        #pragma unroll
        for (int q = 0; q < 8; q++) s[q] = g_sorted[e + q];
        float4 v[8];
        #pragma unroll
        for (int q = 0; q < 8; q++) v[q] = __ldg(&x4[s[q] * 16 + lane]);
        #pragma unroll
        for (int q = 0; q < 8; q++) {
            acc.x += v[q].x; acc.y += v[q].y; acc.z += v[q].z; acc.w += v[q].w;
        }
    }
    for (; e < end; e++) {
        float4 v = __ldg(&x4[g_sorted[e] * 16 + lane]);
        acc.x += v.x; acc.y += v.y; acc.z += v.z; acc.w += v.w;
    }
    ((float4*)g_h)[hw * 16 + lane] = acc;
}

// ---------------- fused MLP: 128-node tiles, 256 threads, f32x2 microkernels ----------------
#define TM 128
#define XPITCH 65   // padded pitch to avoid smem bank conflicts on column reads

__device__ __forceinline__ void gemm64(const float* __restrict__ Xs, const float* __restrict__ Ws,
                                       float* __restrict__ Ys, const float* __restrict__ bias,
                                       int tx, int ty) {
    u64 acc[8][2];
    {
        float2 b01 = *(const float2*)&bias[tx * 4];
        float2 b23 = *(const float2*)&bias[tx * 4 + 2];
        u64 p0 = pack2(b01.x, b01.y), p1 = pack2(b23.x, b23.y);
        #pragma unroll
        for (int i = 0; i < 8; i++) { acc[i][0] = p0; acc[i][1] = p1; }
    }
    #pragma unroll 4
    for (int k = 0; k < 64; k++) {
        u64 b0 = *(const u64*)&Ws[k * 64 + tx * 4];       // packed (b[j0], b[j1])
        u64 b1 = *(const u64*)&Ws[k * 64 + tx * 4 + 2];
        #pragma unroll
        for (int i = 0; i < 8; i++) {
            float a = Xs[(ty * 8 + i) * XPITCH + k];
            u64 ap = pack2(a, a);
            acc[i][0] = fma2(ap, b0, acc[i][0]);
            acc[i][1] = fma2(ap, b1, acc[i][1]);
        }
    }
    #pragma unroll
    for (int i = 0; i < 8; i++) {
        float2 r0 = unpack2(acc[i][0]);
        float2 r1 = unpack2(acc[i][1]);
        float* yp = &Ys[(ty * 8 + i) * XPITCH + tx * 4];
        yp[0] = fmaxf(r0.x, 0.f); yp[1] = fmaxf(r0.y, 0.f);
        yp[2] = fmaxf(r1.x, 0.f); yp[3] = fmaxf(r1.y, 0.f);
    }
}

__device__ __forceinline__ void gemm64_head(const float* __restrict__ Xs, const float* __restrict__ Ws,
                                            const float* __restrict__ bias, const float* __restrict__ wl2,
                                            float* __restrict__ outs, int tx, int ty) {
    u64 acc[8][2];
    {
        float2 b01 = *(const float2*)&bias[tx * 4];
        float2 b23 = *(const float2*)&bias[tx * 4 + 2];
        u64 p0 = pack2(b01.x, b01.y), p1 = pack2(b23.x, b23.y);
        #pragma unroll
        for (int i = 0; i < 8; i++) { acc[i][0] = p0; acc[i][1] = p1; }
    }
    #pragma unroll 4
    for (int k = 0; k < 64; k++) {
        u64 b0 = *(const u64*)&Ws[k * 64 + tx * 4];
        u64 b1 = *(const u64*)&Ws[k * 64 + tx * 4 + 2];
        #pragma unroll
        for (int i = 0; i < 8; i++) {
            float a = Xs[(ty * 8 + i) * XPITCH + k];
            u64 ap = pack2(a, a);
            acc[i][0] = fma2(ap, b0, acc[i][0]);
            acc[i][1] = fma2(ap, b1, acc[i][1]);
        }
    }
    float2 w01 = *(const float2*)&wl2[tx * 4];
    float2 w23 = *(const float2*)&wl2[tx * 4 + 2];
    #pragma unroll
    for (int i = 0; i < 8; i++) {
        float2 r0 = unpack2(acc[i][0]);
        float2 r1 = unpack2(acc[i][1]);
        float s = fmaxf(r0.x, 0.f) * w01.x + fmaxf(r0.y, 0.f) * w01.y
                + fmaxf(r1.x, 0.f) * w23.x + fmaxf(r1.y, 0.f) * w23.y;
        atomicAdd(&outs[ty * 8 + i], s);
    }
}

__global__ void __launch_bounds__(256) k_mlp(
                      const float* __restrict__ W2, const float* __restrict__ b2,
                      const float* __restrict__ Wl1, const float* __restrict__ bl1,
                      const float* __restrict__ Wl2, const float* __restrict__ bl2,
                      float* __restrict__ out) {
    extern __shared__ float sm[];
    float* X    = sm;                       // TM * XPITCH
    float* Y    = X + TM * XPITCH;          // TM * XPITCH
    float* W    = Y + TM * XPITCH;          // 64 * 64
    float* outs = W + 64 * 64;              // TM

    const int tid = threadIdx.x;
    const int tx = tid & 15;
    const int ty = tid >> 4;
    const int base = blockIdx.x * TM;

    // load h tile (float4, zero-padded past N)
    for (int i = tid; i < TM * 16; i += 256) {
        int row = i >> 4, c4 = i & 15;
        int node = base + row;
        float4 v = make_float4(0.f, 0.f, 0.f, 0.f);
        if (node < NNODES) v = ((const float4*)g_h)[node * 16 + c4];
        float* xp = &X[row * XPITCH + c4 * 4];
        xp[0] = v.x; xp[1] = v.y; xp[2] = v.z; xp[3] = v.w;
    }
    for (int i = tid; i < 4096; i += 256) W[i] = g_W1f[i];
    if (tid < TM) outs[tid] = bl2[0];
    __syncthreads();

    // layer 1: Y = relu(BN(X@W1 + b1))  (BN folded)
    gemm64(X, W, Y, g_b1f, tx, ty);
    __syncthreads();

    // layer 2: X = relu(Y@W2 + b2)
    for (int i = tid; i < 4096; i += 256) W[i] = W2[i];
    __syncthreads();
    gemm64(Y, W, X, b2, tx, ty);
    __syncthreads();

    // layers 3+4 fused: out += relu(X@Wl1 + bl1) @ Wl2, in three 64-col chunks
    for (int c = 0; c < 3; c++) {
        for (int i = tid; i < 4096; i += 256) {
            int k = i >> 6, j = i & 63;
            W[i] = Wl1[k * 192 + c * 64 + j];
        }
        __syncthreads();
        gemm64_head(X, W, bl1 + c * 64, Wl2 + c * 64, outs, tx, ty);
        __syncthreads();
    }

    if (tid < TM) {
        int node = base + tid;
        if (node < NNODES) out[node] = outs[tid];
    }
}

// ---------------- launch ----------------
extern "C" void kernel_launch(void* const* d_in, const int* in_sizes, int n_in,
                              void* d_out, int out_size) {
    const float* x     = (const float*)d_in[0];
    const int*   ei    = (const int*)  d_in[1];
    const float* W1    = (const float*)d_in[2];
    const float* b1    = (const float*)d_in[3];
    const float* gamma = (const float*)d_in[4];
    const float* beta  = (const float*)d_in[5];
    const float* mean  = (const float*)d_in[6];
    const float* var   = (const float*)d_in[7];
    const float* W2    = (const float*)d_in[8];
    const float* b2    = (const float*)d_in[9];
    const float* Wl1   = (const float*)d_in[10];
    const float* bl1   = (const float*)d_in[11];
    const float* Wl2   = (const float*)d_in[12];
    const float* bl2   = (const float*)d_in[13];
    float* out = (float*)d_out;

    const int* src = ei;             // edge_index[0]
    const int* dst = ei + NEDGES;    // edge_index[1]

    k_init<<<(NNODES + 255) / 256, 256>>>(W1, b1, gamma, beta, mean, var);
    k_hist<<<(NEDGES / 4 + 255) / 256, 256>>>((const int4*)dst);
    k_scan<<<1, 1024>>>();
    k_scatter<<<(NEDGES / 4 + 255) / 256, 256>>>((const int4*)src, (const int4*)dst);
    k_gather<<<(NNODES * 16 + 255) / 256, 256>>>((const float4*)x);

    const int smem_mlp = (TM * XPITCH * 2 + 64 * 64 + TM) * (int)sizeof(float);
    cudaFuncSetAttribute(k_mlp, cudaFuncAttributeMaxDynamicSharedMemorySize, smem_mlp);
    k_mlp<<<(NNODES + TM - 1) / TM, 256, smem_mlp>>>(W2, b2, Wl1, bl1, Wl2, bl2, out);
}

// round 4
// speedup vs baseline: 1.1413x; 1.1316x over previous
#include <cuda_runtime.h>
#include <cuda_fp16.h>

// Problem constants (fixed-shape problem)
#define NNODES 100000
#define NEDGES 3200000
#define F      64
#define BN_EPS 1e-5f

typedef unsigned long long u64;

// ---------------- device scratch (no runtime allocation allowed) ----------------
__device__ int   g_counts[NNODES];
__device__ int   g_rowptr[NNODES + 1];
__device__ int   g_cursor[NNODES];
__device__ int   g_sorted[NEDGES];
__device__ __align__(16) float   g_h[(size_t)NNODES * F];    // aggregated features (fp32)
__device__ __align__(16) __half2 g_xh[(size_t)NNODES * 32];  // fp16 copy of x
__device__ float g_W1f[F * F];                               // W1 with BN folded
__device__ float g_b1f[F];                                   // b1 with BN folded

// ---------------- f32x2 packed-FMA helpers (Blackwell fp32x2 pipe) ----------------
__device__ __forceinline__ u64 pack2(float a, float b) {
    u64 r; asm("mov.b64 %0, {%1, %2};" : "=l"(r) : "f"(a), "f"(b)); return r;
}
__device__ __forceinline__ float2 unpack2(u64 v) {
    float2 f; asm("mov.b64 {%0, %1}, %2;" : "=f"(f.x), "=f"(f.y) : "l"(v)); return f;
}
__device__ __forceinline__ u64 fma2(u64 a, u64 b, u64 c) {
    u64 d; asm("fma.rn.f32x2 %0, %1, %2, %3;" : "=l"(d) : "l"(a), "l"(b), "l"(c)); return d;
}

// ---------------- init: fold BN into layer-1 affine, zero histogram ----------------
__global__ void k_init(const float* __restrict__ W1, const float* __restrict__ b1,
                       const float* __restrict__ gamma, const float* __restrict__ beta,
                       const float* __restrict__ mean, const float* __restrict__ var) {
    int idx = blockIdx.x * blockDim.x + threadIdx.x;
    if (idx < NNODES) g_counts[idx] = 0;
    if (idx < F * F) {
        int j = idx & (F - 1);
        float s = gamma[j] * rsqrtf(var[j] + BN_EPS);
        g_W1f[idx] = W1[idx] * s;
        if (idx < F) g_b1f[idx] = (b1[idx] - mean[idx]) * s + beta[idx];
    }
}

// ---------------- convert x to fp16 (halves gather L2 traffic) ----------------
__global__ void k_cvt(const float2* __restrict__ x2) {
    int t = blockIdx.x * blockDim.x + threadIdx.x;
    if (t < NNODES * 32) g_xh[t] = __float22half2_rn(x2[t]);
}

// ---------------- histogram of destination degrees (8 edges/thread) ----------------
__global__ void k_hist(const int4* __restrict__ dst4) {
    int t = blockIdx.x * blockDim.x + threadIdx.x;
    if (t < NEDGES / 8) {
        int4 d0 = dst4[t * 2];
        int4 d1 = dst4[t * 2 + 1];
        atomicAdd(&g_counts[d0.x], 1); atomicAdd(&g_counts[d0.y], 1);
        atomicAdd(&g_counts[d0.z], 1); atomicAdd(&g_counts[d0.w], 1);
        atomicAdd(&g_counts[d1.x], 1); atomicAdd(&g_counts[d1.y], 1);
        atomicAdd(&g_counts[d1.z], 1); atomicAdd(&g_counts[d1.w], 1);
    }
}

// ---------------- single-block exclusive scan -> rowptr + cursor ----------------
__global__ void k_scan() {
    __shared__ int s[1024];
    const int t = threadIdx.x;
    const int C = 100;                      // 1000 threads * 100 = 100000
    int beg = t * C;
    int sum = 0;
    if (t < 1000) {
        const int4* c4 = (const int4*)&g_counts[beg];
        #pragma unroll 5
        for (int i = 0; i < C / 4; i++) {
            int4 v = c4[i];
            sum += v.x + v.y + v.z + v.w;
        }
    }
    s[t] = sum;
    __syncthreads();
    for (int off = 1; off < 1024; off <<= 1) {
        int v = (t >= off) ? s[t - off] : 0;
        __syncthreads();
        s[t] += v;
        __syncthreads();
    }
    int run = s[t] - sum;                   // exclusive prefix
    if (t < 1000) {
        for (int i = beg; i < beg + C; i++) {
            g_rowptr[i] = run;
            g_cursor[i] = run;
            run += g_counts[i];
        }
    }
    if (t == 1023) g_rowptr[NNODES] = s[1023];
}

// ---------------- scatter src ids into CSR order (8 edges/thread) ----------------
__global__ void k_scatter(const int4* __restrict__ src4, const int4* __restrict__ dst4) {
    int t = blockIdx.x * blockDim.x + threadIdx.x;
    if (t < NEDGES / 8) {
        int4 s0 = src4[t * 2];
        int4 s1 = src4[t * 2 + 1];
        int4 d0 = dst4[t * 2];
        int4 d1 = dst4[t * 2 + 1];
        g_sorted[atomicAdd(&g_cursor[d0.x], 1)] = s0.x;
        g_sorted[atomicAdd(&g_cursor[d0.y], 1)] = s0.y;
        g_sorted[atomicAdd(&g_cursor[d0.z], 1)] = s0.z;
        g_sorted[atomicAdd(&g_cursor[d0.w], 1)] = s0.w;
        g_sorted[atomicAdd(&g_cursor[d1.x], 1)] = s1.x;
        g_sorted[atomicAdd(&g_cursor[d1.y], 1)] = s1.y;
        g_sorted[atomicAdd(&g_cursor[d1.z], 1)] = s1.z;
        g_sorted[atomicAdd(&g_cursor[d1.w], 1)] = s1.w;
    }
}

// ---------------- gather: 8 lanes/node, fp16 rows (16B/lane/edge), fp32 accum ----------------
__global__ void __launch_bounds__(256) k_gather(const float4* __restrict__ x4) {
    int t = blockIdx.x * blockDim.x + threadIdx.x;
    int node = t >> 3;                       // quarter-warp per node
    int lane = t & 7;                        // features lane*8 .. lane*8+7
    if (node >= NNODES) return;

    // self term exact fp32
    float4 s0 = __ldg(&x4[node * 16 + lane * 2]);
    float4 s1 = __ldg(&x4[node * 16 + lane * 2 + 1]);
    float2 a0 = make_float2(s0.x, s0.y), a1 = make_float2(s0.z, s0.w);
    float2 a2 = make_float2(s1.x, s1.y), a3 = make_float2(s1.z, s1.w);

    const uint4* __restrict__ xh = (const uint4*)g_xh;   // 8 half2 per node-lane chunk
    int beg = g_rowptr[node];
    int end = g_rowptr[node + 1];
    int e = beg;
    for (; e + 8 <= end; e += 8) {
        int idx[8];
        #pragma unroll
        for (int q = 0; q < 8; q++) idx[q] = g_sorted[e + q];
        uint4 v[8];
        #pragma unroll
        for (int q = 0; q < 8; q++) v[q] = __ldg(&xh[idx[q] * 8 + lane]);
        #pragma unroll
        for (int q = 0; q < 8; q++) {
            float2 f0 = __half22float2(*(const __half2*)&v[q].x);
            float2 f1 = __half22float2(*(const __half2*)&v[q].y);
            float2 f2 = __half22float2(*(const __half2*)&v[q].z);
            float2 f3 = __half22float2(*(const __half2*)&v[q].w);
            a0.x += f0.x; a0.y += f0.y; a1.x += f1.x; a1.y += f1.y;
            a2.x += f2.x; a2.y += f2.y; a3.x += f3.x; a3.y += f3.y;
        }
    }
    for (; e < end; e++) {
        uint4 v = __ldg(&xh[g_sorted[e] * 8 + lane]);
        float2 f0 = __half22float2(*(const __half2*)&v.x);
        float2 f1 = __half22float2(*(const __half2*)&v.y);
        float2 f2 = __half22float2(*(const __half2*)&v.z);
        float2 f3 = __half22float2(*(const __half2*)&v.w);
        a0.x += f0.x; a0.y += f0.y; a1.x += f1.x; a1.y += f1.y;
        a2.x += f2.x; a2.y += f2.y; a3.x += f3.x; a3.y += f3.y;
    }
    float4* hp = (float4*)g_h;
    hp[node * 16 + lane * 2]     = make_float4(a0.x, a0.y, a1.x, a1.y);
    hp[node * 16 + lane * 2 + 1] = make_float4(a2.x, a2.y, a3.x, a3.y);
}

// ---------------- fused MLP: 128-node tiles, 128 threads, 8x8 f32x2 microtiles ----------------
#define TM 128
#define XP 66   // 64 + 2 pad: conflict-light column reads, float2-aligned rows

__device__ __forceinline__ void gemm64(const float* __restrict__ Xs, const float* __restrict__ Ws,
                                       float* __restrict__ Ys, const float* __restrict__ bias,
                                       int tx, int ty) {
    u64 acc[8][4];
    {
        const u64* bp = (const u64*)&bias[tx * 8];
        u64 c0 = bp[0], c1 = bp[1], c2 = bp[2], c3 = bp[3];
        #pragma unroll
        for (int i = 0; i < 8; i++) { acc[i][0] = c0; acc[i][1] = c1; acc[i][2] = c2; acc[i][3] = c3; }
    }
    #pragma unroll 8
    for (int k = 0; k < 64; k++) {
        const u64* wp = (const u64*)&Ws[k * 64 + tx * 8];
        u64 b0 = wp[0], b1 = wp[1], b2 = wp[2], b3 = wp[3];
        #pragma unroll
        for (int i = 0; i < 8; i++) {
            float a = Xs[(ty * 8 + i) * XP + k];     // broadcast among 8 tx-threads
            u64 ap = pack2(a, a);
            acc[i][0] = fma2(ap, b0, acc[i][0]);
            acc[i][1] = fma2(ap, b1, acc[i][1]);
            acc[i][2] = fma2(ap, b2, acc[i][2]);
            acc[i][3] = fma2(ap, b3, acc[i][3]);
        }
    }
    #pragma unroll
    for (int i = 0; i < 8; i++) {
        float* yp = &Ys[(ty * 8 + i) * XP + tx * 8];
        #pragma unroll
        for (int jp = 0; jp < 4; jp++) {
            float2 r = unpack2(acc[i][jp]);
            *(float2*)&yp[jp * 2] = make_float2(fmaxf(r.x, 0.f), fmaxf(r.y, 0.f));
        }
    }
}

__device__ __forceinline__ void gemm64_head(const float* __restrict__ Xs, const float* __restrict__ Ws,
                                            const float* __restrict__ bias, const float* __restrict__ wl2,
                                            float* __restrict__ outs, int tx, int ty) {
    u64 acc[8][4];
    {
        const u64* bp = (const u64*)&bias[tx * 8];
        u64 c0 = bp[0], c1 = bp[1], c2 = bp[2], c3 = bp[3];
        #pragma unroll
        for (int i = 0; i < 8; i++) { acc[i][0] = c0; acc[i][1] = c1; acc[i][2] = c2; acc[i][3] = c3; }
    }
    #pragma unroll 8
    for (int k = 0; k < 64; k++) {
        const u64* wp = (const u64*)&Ws[k * 64 + tx * 8];
        u64 b0 = wp[0], b1 = wp[1], b2 = wp[2], b3 = wp[3];
        #pragma unroll
        for (int i = 0; i < 8; i++) {
            float a = Xs[(ty * 8 + i) * XP + k];
            u64 ap = pack2(a, a);
            acc[i][0] = fma2(ap, b0, acc[i][0]);
            acc[i][1] = fma2(ap, b1, acc[i][1]);
            acc[i][2] = fma2(ap, b2, acc[i][2]);
            acc[i][3] = fma2(ap, b3, acc[i][3]);
        }
    }
    float w[8];
    #pragma unroll
    for (int j = 0; j < 8; j++) w[j] = wl2[tx * 8 + j];
    #pragma unroll
    for (int i = 0; i < 8; i++) {
        float s = 0.f;
        #pragma unroll
        for (int jp = 0; jp < 4; jp++) {
            float2 r = unpack2(acc[i][jp]);
            s += fmaxf(r.x, 0.f) * w[jp * 2] + fmaxf(r.y, 0.f) * w[jp * 2 + 1];
        }
        // reduce across the 8 tx-lanes (contiguous within warp)
        s += __shfl_xor_sync(0xffffffffu, s, 1);
        s += __shfl_xor_sync(0xffffffffu, s, 2);
        s += __shfl_xor_sync(0xffffffffu, s, 4);
        if (tx == 0) outs[ty * 8 + i] += s;   // single writer per row
    }
}

__global__ void __launch_bounds__(128, 2) k_mlp(
                      const float* __restrict__ W2, const float* __restrict__ b2,
                      const float* __restrict__ Wl1, const float* __restrict__ bl1,
                      const float* __restrict__ Wl2, const float* __restrict__ bl2,
                      float* __restrict__ out) {
    extern __shared__ float sm[];
    float* X    = sm;                       // TM * XP
    float* Y    = X + TM * XP;              // TM * XP
    float* W    = Y + TM * XP;              // 64 * 64
    float* outs = W + 64 * 64;              // TM

    const int tid = threadIdx.x;
    const int tx = tid & 7;                 // 8 col-groups of 8
    const int ty = tid >> 3;                // 16 row-groups of 8
    const int base = blockIdx.x * TM;

    // load h tile (float2 granularity keeps XP=66 rows aligned), zero-pad past N
    const float2* h2 = (const float2*)g_h;
    for (int i = tid; i < TM * 32; i += 128) {
        int row = i >> 5, c2 = i & 31;
        int node = base + row;
        float2 v = make_float2(0.f, 0.f);
        if (node < NNODES) v = h2[node * 32 + c2];
        *(float2*)&X[row * XP + c2 * 2] = v;
    }
    for (int i = tid; i < 1024; i += 128) ((float4*)W)[i] = ((const float4*)g_W1f)[i];
    if (tid < TM) outs[tid] = bl2[0];
    __syncthreads();

    // layer 1: Y = relu(BN(X@W1 + b1))  (BN folded)
    gemm64(X, W, Y, g_b1f, tx, ty);
    __syncthreads();

    // layer 2: X = relu(Y@W2 + b2)
    for (int i = tid; i < 1024; i += 128) ((float4*)W)[i] = ((const float4*)W2)[i];
    __syncthreads();
    gemm64(Y, W, X, b2, tx, ty);
    __syncthreads();

    // layers 3+4 fused: out += relu(X@Wl1 + bl1) @ Wl2, in three 64-col chunks
    for (int c = 0; c < 3; c++) {
        for (int i = tid; i < 4096; i += 128) {
            int k = i >> 6, j = i & 63;
            W[i] = Wl1[k * 192 + c * 64 + j];
        }
        __syncthreads();
        gemm64_head(X, W, bl1 + c * 64, Wl2 + c * 64, outs, tx, ty);
        __syncthreads();
    }

    if (tid < TM) {
        int node = base + tid;
        if (node < NNODES) out[node] = outs[tid];
    }
}

// ---------------- launch ----------------
extern "C" void kernel_launch(void* const* d_in, const int* in_sizes, int n_in,
                              void* d_out, int out_size) {
    const float* x     = (const float*)d_in[0];
    const int*   ei    = (const int*)  d_in[1];
    const float* W1    = (const float*)d_in[2];
    const float* b1    = (const float*)d_in[3];
    const float* gamma = (const float*)d_in[4];
    const float* beta  = (const float*)d_in[5];
    const float* mean  = (const float*)d_in[6];
    const float* var   = (const float*)d_in[7];
    const float* W2    = (const float*)d_in[8];
    const float* b2    = (const float*)d_in[9];
    const float* Wl1   = (const float*)d_in[10];
    const float* bl1   = (const float*)d_in[11];
    const float* Wl2   = (const float*)d_in[12];
    const float* bl2   = (const float*)d_in[13];
    float* out = (float*)d_out;

    const int* src = ei;             // edge_index[0]
    const int* dst = ei + NEDGES;    // edge_index[1]

    k_init<<<(NNODES + 255) / 256, 256>>>(W1, b1, gamma, beta, mean, var);
    k_cvt<<<(NNODES * 32 + 255) / 256, 256>>>((const float2*)x);
    k_hist<<<(NEDGES / 8 + 255) / 256, 256>>>((const int4*)dst);
    k_scan<<<1, 1024>>>();
    k_scatter<<<(NEDGES / 8 + 255) / 256, 256>>>((const int4*)src, (const int4*)dst);
    k_gather<<<(NNODES * 8 + 255) / 256, 256>>>((const float4*)x);

    const int smem_mlp = (TM * XP * 2 + 64 * 64 + TM) * (int)sizeof(float);
    cudaFuncSetAttribute(k_mlp, cudaFuncAttributeMaxDynamicSharedMemorySize, smem_mlp);
    k_mlp<<<(NNODES + TM - 1) / TM, 128, smem_mlp>>>(W2, b2, Wl1, bl1, Wl2, bl2, out);
}

// round 6
// speedup vs baseline: 1.9082x; 1.6720x over previous
#include <cuda_runtime.h>
#include <cuda_fp16.h>

// Problem constants (fixed-shape problem)
#define NNODES 100000
#define NEDGES 3200000
#define F      64
#define BN_EPS 1e-5f

#define NQ4    (NNODES / 4)          // 25000 int4 chunks of counts
#define SCAN_T 512
#define SCAN_B ((NQ4 + SCAN_T - 1) / SCAN_T)   // 49 blocks

typedef unsigned long long u64;

// ---------------- device scratch (no runtime allocation allowed) ----------------
__device__ __align__(16) int g_counts[NNODES];
__device__ __align__(16) int g_rowptr[NNODES + 4];   // +pad so int4 stores stay in-bounds
__device__ __align__(16) int g_cursor[NNODES];
__device__ int   g_bsum[SCAN_B];
__device__ int   g_boff[SCAN_B];
__device__ int   g_sorted[NEDGES];
__device__ __align__(16) float   g_h[(size_t)NNODES * F];    // aggregated features (fp32)
__device__ __align__(16) __half2 g_xh[(size_t)NNODES * 32];  // fp16 copy of x
__device__ float g_W1f[F * F];                               // W1 with BN folded
__device__ float g_b1f[F];                                   // b1 with BN folded

// ---------------- f32x2 packed-FMA helpers (Blackwell fp32x2 pipe) ----------------
__device__ __forceinline__ u64 pack2(float a, float b) {
    u64 r; asm("mov.b64 %0, {%1, %2};" : "=l"(r) : "f"(a), "f"(b)); return r;
}
__device__ __forceinline__ float2 unpack2(u64 v) {
    float2 f; asm("mov.b64 {%0, %1}, %2;" : "=f"(f.x), "=f"(f.y) : "l"(v)); return f;
}
__device__ __forceinline__ u64 fma2(u64 a, u64 b, u64 c) {
    u64 d; asm("fma.rn.f32x2 %0, %1, %2, %3;" : "=l"(d) : "l"(a), "l"(b), "l"(c)); return d;
}

// ---------------- init: fold BN into layer-1 affine, zero histogram ----------------
__global__ void k_init(const float* __restrict__ W1, const float* __restrict__ b1,
                       const float* __restrict__ gamma, const float* __restrict__ beta,
                       const float* __restrict__ mean, const float* __restrict__ var) {
    int idx = blockIdx.x * blockDim.x + threadIdx.x;
    if (idx < NNODES) g_counts[idx] = 0;
    if (idx < F * F) {
        int j = idx & (F - 1);
        float s = gamma[j] * rsqrtf(var[j] + BN_EPS);
        g_W1f[idx] = W1[idx] * s;
        if (idx < F) g_b1f[idx] = (b1[idx] - mean[idx]) * s + beta[idx];
    }
}

// ---------------- convert x to fp16 (halves gather L2 traffic) ----------------
__global__ void k_cvt(const float2* __restrict__ x2) {
    int t = blockIdx.x * blockDim.x + threadIdx.x;
    if (t < NNODES * 32) g_xh[t] = __float22half2_rn(x2[t]);
}

// ---------------- histogram of destination degrees (8 edges/thread) ----------------
__global__ void k_hist(const int4* __restrict__ dst4) {
    int t = blockIdx.x * blockDim.x + threadIdx.x;
    if (t < NEDGES / 8) {
        int4 d0 = dst4[t * 2];
        int4 d1 = dst4[t * 2 + 1];
        atomicAdd(&g_counts[d0.x], 1); atomicAdd(&g_counts[d0.y], 1);
        atomicAdd(&g_counts[d0.z], 1); atomicAdd(&g_counts[d0.w], 1);
        atomicAdd(&g_counts[d1.x], 1); atomicAdd(&g_counts[d1.y], 1);
        atomicAdd(&g_counts[d1.z], 1); atomicAdd(&g_counts[d1.w], 1);
    }
}

// ---------------- 3-phase grid-wide exclusive scan ----------------
__global__ void k_scanA() {
    int g = blockIdx.x * SCAN_T + threadIdx.x;
    int sum = 0;
    if (g < NQ4) {
        int4 v = ((const int4*)g_counts)[g];
        sum = v.x + v.y + v.z + v.w;
    }
    #pragma unroll
    for (int o = 16; o; o >>= 1) sum += __shfl_down_sync(0xffffffffu, sum, o);
    __shared__ int ws[SCAN_T / 32];
    if ((threadIdx.x & 31) == 0) ws[threadIdx.x >> 5] = sum;
    __syncthreads();
    if (threadIdx.x < SCAN_T / 32) {
        int s = ws[threadIdx.x];
        #pragma unroll
        for (int o = 8; o; o >>= 1) s += __shfl_down_sync(0xffffu, s, o);
        if (threadIdx.x == 0) g_bsum[blockIdx.x] = s;
    }
}

__global__ void k_scanB() {
    __shared__ int s[SCAN_B];
    int t = threadIdx.x;
    if (t < SCAN_B) s[t] = g_bsum[t];
    __syncthreads();
    if (t == 0) {
        int run = 0;
        for (int i = 0; i < SCAN_B; i++) { int v = s[i]; g_boff[i] = run; run += v; }
        g_rowptr[NNODES] = run;       // == NEDGES
    }
}

__global__ void k_scanC() {
    const int t = threadIdx.x;
    const int lane = t & 31, warp = t >> 5;
    int g = blockIdx.x * SCAN_T + t;
    int4 v = make_int4(0, 0, 0, 0);
    if (g < NQ4) v = ((const int4*)g_counts)[g];
    int tsum = v.x + v.y + v.z + v.w;
    // inclusive warp scan of thread sums
    int sc = tsum;
    #pragma unroll
    for (int o = 1; o < 32; o <<= 1) {
        int n = __shfl_up_sync(0xffffffffu, sc, o);
        if (lane >= o) sc += n;
    }
    __shared__ int ws[SCAN_T / 32];
    if (lane == 31) ws[warp] = sc;
    __syncthreads();
    if (t < SCAN_T / 32) {
        int s = ws[t];
        #pragma unroll
        for (int o = 1; o < 16; o <<= 1) {
            int n = __shfl_up_sync(0xffffu, s, o);
            if (t >= o) s += n;
        }
        ws[t] = s;
    }
    __syncthreads();
    int base = g_boff[blockIdx.x] + (warp ? ws[warp - 1] : 0) + (sc - tsum);
    if (g < NQ4) {
        int4 r;
        r.x = base;
        r.y = r.x + v.x;
        r.z = r.y + v.y;
        r.w = r.z + v.z;
        ((int4*)g_rowptr)[g] = r;
        ((int4*)g_cursor)[g] = r;
    }
}

// ---------------- scatter src ids into CSR order (8 edges/thread) ----------------
__global__ void k_scatter(const int4* __restrict__ src4, const int4* __restrict__ dst4) {
    int t = blockIdx.x * blockDim.x + threadIdx.x;
    if (t < NEDGES / 8) {
        int4 s0 = src4[t * 2];
        int4 s1 = src4[t * 2 + 1];
        int4 d0 = dst4[t * 2];
        int4 d1 = dst4[t * 2 + 1];
        g_sorted[atomicAdd(&g_cursor[d0.x], 1)] = s0.x;
        g_sorted[atomicAdd(&g_cursor[d0.y], 1)] = s0.y;
        g_sorted[atomicAdd(&g_cursor[d0.z], 1)] = s0.z;
        g_sorted[atomicAdd(&g_cursor[d0.w], 1)] = s0.w;
        g_sorted[atomicAdd(&g_cursor[d1.x], 1)] = s1.x;
        g_sorted[atomicAdd(&g_cursor[d1.y], 1)] = s1.y;
        g_sorted[atomicAdd(&g_cursor[d1.z], 1)] = s1.z;
        g_sorted[atomicAdd(&g_cursor[d1.w], 1)] = s1.w;
    }
}

// ---------------- gather: 8 lanes/node, fp16 rows (16B/lane/edge), fp32 accum ----------------
__global__ void __launch_bounds__(256) k_gather(const float4* __restrict__ x4) {
    int t = blockIdx.x * blockDim.x + threadIdx.x;
    int node = t >> 3;                       // quarter-warp per node
    int lane = t & 7;                        // features lane*8 .. lane*8+7
    if (node >= NNODES) return;

    // self term exact fp32
    float4 s0 = __ldg(&x4[node * 16 + lane * 2]);
    float4 s1 = __ldg(&x4[node * 16 + lane * 2 + 1]);
    float2 a0 = make_float2(s0.x, s0.y), a1 = make_float2(s0.z, s0.w);
    float2 a2 = make_float2(s1.x, s1.y), a3 = make_float2(s1.z, s1.w);

    const uint4* __restrict__ xh = (const uint4*)g_xh;   // 8 half2 per node-lane chunk
    int beg = g_rowptr[node];
    int end = g_rowptr[node + 1];
    int e = beg;
    for (; e + 8 <= end; e += 8) {
        int idx[8];
        #pragma unroll
        for (int q = 0; q < 8; q++) idx[q] = g_sorted[e + q];
        uint4 v[8];
        #pragma unroll
        for (int q = 0; q < 8; q++) v[q] = __ldg(&xh[idx[q] * 8 + lane]);
        #pragma unroll
        for (int q = 0; q < 8; q++) {
            float2 f0 = __half22float2(*(const __half2*)&v[q].x);
            float2 f1 = __half22float2(*(const __half2*)&v[q].y);
            float2 f2 = __half22float2(*(const __half2*)&v[q].z);
            float2 f3 = __half22float2(*(const __half2*)&v[q].w);
            a0.x += f0.x; a0.y += f0.y; a1.x += f1.x; a1.y += f1.y;
            a2.x += f2.x; a2.y += f2.y; a3.x += f3.x; a3.y += f3.y;
        }
    }
    for (; e < end; e++) {
        uint4 v = __ldg(&xh[g_sorted[e] * 8 + lane]);
        float2 f0 = __half22float2(*(const __half2*)&v.x);
        float2 f1 = __half22float2(*(const __half2*)&v.y);
        float2 f2 = __half22float2(*(const __half2*)&v.z);
        float2 f3 = __half22float2(*(const __half2*)&v.w);
        a0.x += f0.x; a0.y += f0.y; a1.x += f1.x; a1.y += f1.y;
        a2.x += f2.x; a2.y += f2.y; a3.x += f3.x; a3.y += f3.y;
    }
    float4* hp = (float4*)g_h;
    hp[node * 16 + lane * 2]     = make_float4(a0.x, a0.y, a1.x, a1.y);
    hp[node * 16 + lane * 2 + 1] = make_float4(a2.x, a2.y, a3.x, a3.y);
}

// ---------------- fused MLP: 128-node tiles, 128 threads, 8x8 f32x2 microtiles ----------------
#define TM 128
#define XP 66   // 64 + 2 pad: conflict-light column reads, float2-aligned rows

__device__ __forceinline__ void gemm64(const float* __restrict__ Xs, const float* __restrict__ Ws,
                                       float* __restrict__ Ys, const float* __restrict__ bias,
                                       int tx, int ty) {
    u64 acc[8][4];
    {
        const u64* bp = (const u64*)&bias[tx * 8];
        u64 c0 = bp[0], c1 = bp[1], c2 = bp[2], c3 = bp[3];
        #pragma unroll
        for (int i = 0; i < 8; i++) { acc[i][0] = c0; acc[i][1] = c1; acc[i][2] = c2; acc[i][3] = c3; }
    }
    #pragma unroll 8
    for (int k = 0; k < 64; k++) {
        const u64* wp = (const u64*)&Ws[k * 64 + tx * 8];
        u64 b0 = wp[0], b1 = wp[1], b2 = wp[2], b3 = wp[3];
        #pragma unroll
        for (int i = 0; i < 8; i++) {
            float a = Xs[(ty * 8 + i) * XP + k];     // broadcast among 8 tx-threads
            u64 ap = pack2(a, a);
            acc[i][0] = fma2(ap, b0, acc[i][0]);
            acc[i][1] = fma2(ap, b1, acc[i][1]);
            acc[i][2] = fma2(ap, b2, acc[i][2]);
            acc[i][3] = fma2(ap, b3, acc[i][3]);
        }
    }
    #pragma unroll
    for (int i = 0; i < 8; i++) {
        float* yp = &Ys[(ty * 8 + i) * XP + tx * 8];
        #pragma unroll
        for (int jp = 0; jp < 4; jp++) {
            float2 r = unpack2(acc[i][jp]);
            *(float2*)&yp[jp * 2] = make_float2(fmaxf(r.x, 0.f), fmaxf(r.y, 0.f));
        }
    }
}

__device__ __forceinline__ void gemm64_head(const float* __restrict__ Xs, const float* __restrict__ Ws,
                                            const float* __restrict__ bias, const float* __restrict__ wl2,
                                            float* __restrict__ outs, int tx, int ty) {
    u64 acc[8][4];
    {
        const u64* bp = (const u64*)&bias[tx * 8];
        u64 c0 = bp[0], c1 = bp[1], c2 = bp[2], c3 = bp[3];
        #pragma unroll
        for (int i = 0; i < 8; i++) { acc[i][0] = c0; acc[i][1] = c1; acc[i][2] = c2; acc[i][3] = c3; }
    }
    #pragma unroll 8
    for (int k = 0; k < 64; k++) {
        const u64* wp = (const u64*)&Ws[k * 64 + tx * 8];
        u64 b0 = wp[0], b1 = wp[1], b2 = wp[2], b3 = wp[3];
        #pragma unroll
        for (int i = 0; i < 8; i++) {
            float a = Xs[(ty * 8 + i) * XP + k];
            u64 ap = pack2(a, a);
            acc[i][0] = fma2(ap, b0, acc[i][0]);
            acc[i][1] = fma2(ap, b1, acc[i][1]);
            acc[i][2] = fma2(ap, b2, acc[i][2]);
            acc[i][3] = fma2(ap, b3, acc[i][3]);
        }
    }
    float w[8];
    #pragma unroll
    for (int j = 0; j < 8; j++) w[j] = wl2[tx * 8 + j];
    #pragma unroll
    for (int i = 0; i < 8; i++) {
        float s = 0.f;
        #pragma unroll
        for (int jp = 0; jp < 4; jp++) {
            float2 r = unpack2(acc[i][jp]);
            s += fmaxf(r.x, 0.f) * w[jp * 2] + fmaxf(r.y, 0.f) * w[jp * 2 + 1];
        }
        // reduce across the 8 tx-lanes (contiguous within warp)
        s += __shfl_xor_sync(0xffffffffu, s, 1);
        s += __shfl_xor_sync(0xffffffffu, s, 2);
        s += __shfl_xor_sync(0xffffffffu, s, 4);
        if (tx == 0) outs[ty * 8 + i] += s;   // single writer per row
    }
}

__global__ void __launch_bounds__(128, 2) k_mlp(
                      const float* __restrict__ W2, const float* __restrict__ b2,
                      const float* __restrict__ Wl1, const float* __restrict__ bl1,
                      const float* __restrict__ Wl2, const float* __restrict__ bl2,
                      float* __restrict__ out) {
    extern __shared__ float sm[];
    float* X    = sm;                       // TM * XP
    float* Y    = X + TM * XP;              // TM * XP
    float* W    = Y + TM * XP;              // 64 * 64
    float* outs = W + 64 * 64;              // TM

    const int tid = threadIdx.x;
    const int tx = tid & 7;                 // 8 col-groups of 8
    const int ty = tid >> 3;                // 16 row-groups of 8
    const int base = blockIdx.x * TM;

    // load h tile (float2 granularity keeps XP=66 rows aligned), zero-pad past N
    const float2* h2 = (const float2*)g_h;
    for (int i = tid; i < TM * 32; i += 128) {
        int row = i >> 5, c2 = i & 31;
        int node = base + row;
        float2 v = make_float2(0.f, 0.f);
        if (node < NNODES) v = h2[node * 32 + c2];
        *(float2*)&X[row * XP + c2 * 2] = v;
    }
    for (int i = tid; i < 1024; i += 128) ((float4*)W)[i] = ((const float4*)g_W1f)[i];
    if (tid < TM) outs[tid] = bl2[0];
    __syncthreads();

    // layer 1: Y = relu(BN(X@W1 + b1))  (BN folded)
    gemm64(X, W, Y, g_b1f, tx, ty);
    __syncthreads();

    // layer 2: X = relu(Y@W2 + b2)
    for (int i = tid; i < 1024; i += 128) ((float4*)W)[i] = ((const float4*)W2)[i];
    __syncthreads();
    gemm64(Y, W, X, b2, tx, ty);
    __syncthreads();

    // layers 3+4 fused: out += relu(X@Wl1 + bl1) @ Wl2, in three 64-col chunks
    for (int c = 0; c < 3; c++) {
        for (int i = tid; i < 4096; i += 128) {
            int k = i >> 6, j = i & 63;
            W[i] = Wl1[k * 192 + c * 64 + j];
        }
        __syncthreads();
        gemm64_head(X, W, bl1 + c * 64, Wl2 + c * 64, outs, tx, ty);
        __syncthreads();
    }

    if (tid < TM) {
        int node = base + tid;
        if (node < NNODES) out[node] = outs[tid];
    }
}

// ---------------- launch ----------------
extern "C" void kernel_launch(void* const* d_in, const int* in_sizes, int n_in,
                              void* d_out, int out_size) {
    const float* x     = (const float*)d_in[0];
    const int*   ei    = (const int*)  d_in[1];
    const float* W1    = (const float*)d_in[2];
    const float* b1    = (const float*)d_in[3];
    const float* gamma = (const float*)d_in[4];
    const float* beta  = (const float*)d_in[5];
    const float* mean  = (const float*)d_in[6];
    const float* var   = (const float*)d_in[7];
    const float* W2    = (const float*)d_in[8];
    const float* b2    = (const float*)d_in[9];
    const float* Wl1   = (const float*)d_in[10];
    const float* bl1   = (const float*)d_in[11];
    const float* Wl2   = (const float*)d_in[12];
    const float* bl2   = (const float*)d_in[13];
    float* out = (float*)d_out;

    const int* src = ei;             // edge_index[0]
    const int* dst = ei + NEDGES;    // edge_index[1]

    k_init<<<(NNODES + 255) / 256, 256>>>(W1, b1, gamma, beta, mean, var);
    k_cvt<<<(NNODES * 32 + 255) / 256, 256>>>((const float2*)x);
    k_hist<<<(NEDGES / 8 + 255) / 256, 256>>>((const int4*)dst);
    k_scanA<<<SCAN_B, SCAN_T>>>();
    k_scanB<<<1, 64>>>();
    k_scanC<<<SCAN_B, SCAN_T>>>();
    k_scatter<<<(NEDGES / 8 + 255) / 256, 256>>>((const int4*)src, (const int4*)dst);
    k_gather<<<(NNODES * 8 + 255) / 256, 256>>>((const float4*)x);

    const int smem_mlp = (TM * XP * 2 + 64 * 64 + TM) * (int)sizeof(float);
    cudaFuncSetAttribute(k_mlp, cudaFuncAttributeMaxDynamicSharedMemorySize, smem_mlp);
    k_mlp<<<(NNODES + TM - 1) / TM, 128, smem_mlp>>>(W2, b2, Wl1, bl1, Wl2, bl2, out);
}